// round 13
// baseline (speedup 1.0000x reference)
#include <cuda_runtime.h>
#include <cuda_fp16.h>
#include <cstdint>

#define B_DIM 64
#define L_DIM 8192
#define C_DIM 128
#define NCH   64
#define GRID_DENSE 296                 // 2 CTAs/SM x 148 SMs, exactly 1 wave
#define CHUNK 14                       // tiles per CTA
#define MAX_TILES (GRID_DENSE * CHUNK) // 4144 >= worst-case 4128 real tiles

static __device__ int g_tile_l0[MAX_TILES];
static __device__ int g_tile_l1[MAX_TILES];
static __device__ int g_tile_ch[MAX_TILES];

// ---------------- helpers ----------------
__device__ __forceinline__ uint32_t smem_u32(const void* p) {
    uint32_t a;
    asm("{ .reg .u64 t; cvta.to.shared.u64 t, %1; cvt.u32.u64 %0, t; }" : "=r"(a) : "l"(p));
    return a;
}
__device__ __forceinline__ float tanh_fast(float v) {
    float r; asm("tanh.approx.f32 %0, %1;" : "=f"(r) : "f"(v)); return r;
}
__device__ __forceinline__ void mma_f16(float* d, const uint32_t* a, const uint32_t* b) {
    asm volatile(
        "mma.sync.aligned.m16n8k16.row.col.f32.f16.f16.f32 "
        "{%0,%1,%2,%3}, {%4,%5,%6,%7}, {%8,%9}, {%0,%1,%2,%3};"
        : "+f"(d[0]), "+f"(d[1]), "+f"(d[2]), "+f"(d[3])
        : "r"(a[0]), "r"(a[1]), "r"(a[2]), "r"(a[3]), "r"(b[0]), "r"(b[1]));
}
__device__ __forceinline__ void ldsm_x4(uint32_t* r, uint32_t addr) {
    asm volatile("ldmatrix.sync.aligned.m8n8.x4.shared.b16 {%0,%1,%2,%3}, [%4];"
        : "=r"(r[0]), "=r"(r[1]), "=r"(r[2]), "=r"(r[3]) : "r"(addr));
}

// ---------------- prep_all: one launch does everything ----------------
__global__ void prep_all(const void* __restrict__ chan_raw, float* __restrict__ tail_out) {
    __shared__ int s_cnt[NCH], s_start[NCH], s_cur[NCH], s_ts[NCH];
    __shared__ int s_zcnt;
    extern __shared__ int s_sorted[];              // 8192 ints (32 KB dynamic)
    int t = threadIdx.x;                           // 1024 threads

    if (t == 0) s_zcnt = 0;
    if (t < NCH) s_cnt[t] = 0;
    for (int i = t; i < MAX_TILES; i += 1024) g_tile_ch[i] = -1;
    __syncthreads();

    if (t < 256) {                                 // dtype sniff
        const int* w32 = (const int*)chan_raw;
        int z = (w32[2 * t + 1] == 0);
        unsigned m = __ballot_sync(0xFFFFFFFF, z);
        if ((t & 31) == 0) atomicAdd(&s_zcnt, __popc(m));
    }
    __syncthreads();
    int is64 = s_zcnt > 128;

    const long long* c64 = (const long long*)chan_raw;
    const int*       c32 = (const int*)chan_raw;

    for (int i = t; i < L_DIM; i += 1024) {        // histogram + channels tail
        long long v = is64 ? c64[i] : (long long)c32[i];
        tail_out[i] = (float)v;
        atomicAdd(&s_cnt[(int)v & (NCH - 1)], 1);
    }
    __syncthreads();

    if (t == 0) {
        int s = 0, ts = 0;
        for (int g = 0; g < NCH; g++) {
            s_start[g] = s; s_cur[g] = s; s_ts[g] = ts;
            s += s_cnt[g]; ts += (s_cnt[g] + 1) >> 1;
        }
    }
    __syncthreads();

    for (int i = t; i < L_DIM; i += 1024) {        // scatter
        int c = (int)(is64 ? c64[i] : (long long)c32[i]) & (NCH - 1);
        int p = atomicAdd(&s_cur[c], 1);
        s_sorted[p] = i;
    }
    __syncthreads();

    int g = t >> 4, j = t & 15;                    // tile build
    int s0 = s_start[g], c = s_cnt[g], ts = s_ts[g];
    for (int i = j; i < (c + 1) / 2; i += 16) {
        g_tile_l0[ts + i] = s_sorted[s0 + 2 * i];
        g_tile_l1[ts + i] = (2 * i + 1 < c) ? s_sorted[s0 + 2 * i + 1] : -1;
        g_tile_ch[ts + i] = g;
    }
}

// ---------------- dense kernel: 512 threads, 64-reg budget, 2 CTAs/SM ----------------
static constexpr int SROWH = 136;                 // fp16 row stride (halfs)
static constexpr int WHBYTES = C_DIM * SROWH * 2; // 34816
static constexpr int WH_OFF  = 0;
static constexpr int XH0_OFF = WHBYTES;
static constexpr int XH1_OFF = 2 * WHBYTES;
static constexpr int SMEM_TOTAL = 3 * WHBYTES;    // 104448 B -> 2 CTAs/SM

// X tile: LDG.128 fp32 -> RN fp16 -> STS.64 (8 float4 / thread @512 thr)
__device__ __forceinline__ void load_x(__half* Xh, const float* __restrict__ x,
                                       int l0, int l1, int tid) {
    #pragma unroll
    for (int i = 0; i < 8; i++) {
        int f = tid + (i << 9);                    // 0..4095 float4s
        int row = f >> 5, k4 = (f & 31) << 2;      // row uniform per warp
        int l = (row >= 64) ? l1 : l0;
        if (l < 0) continue;
        int b = row & 63;
        float4 v = *reinterpret_cast<const float4*>(x + ((size_t)b * L_DIM + l) * C_DIM + k4);
        __half2 h0 = __floats2half2_rn(v.x, v.y);
        __half2 h1 = __floats2half2_rn(v.z, v.w);
        *reinterpret_cast<uint2*>(Xh + row * SROWH + k4) =
            make_uint2(*(uint32_t*)&h0, *(uint32_t*)&h1);
    }
}
__device__ __forceinline__ void load_w(__half* Wh, const float* __restrict__ weight,
                                       int ch, int tid) {
    const float4* Wsrc = reinterpret_cast<const float4*>(weight + (size_t)ch * (C_DIM * C_DIM));
    #pragma unroll
    for (int i = 0; i < 8; i++) {
        int f = tid + (i << 9);
        float4 v = Wsrc[f];
        __half2 h0 = __floats2half2_rn(v.x, v.y);
        __half2 h1 = __floats2half2_rn(v.z, v.w);
        *reinterpret_cast<uint2*>(Wh + (f >> 5) * SROWH + ((f & 31) << 2)) =
            make_uint2(*(uint32_t*)&h0, *(uint32_t*)&h1);
    }
}

__global__ void __launch_bounds__(512, 2) dense_kernel(
    const float* __restrict__ x, const float* __restrict__ weight,
    const float* __restrict__ bias, float* __restrict__ out)
{
    int base = blockIdx.x * CHUNK;
    int ch0 = g_tile_ch[base];
    if (ch0 < 0) return;

    extern __shared__ char smem[];
    __half* Wh    = reinterpret_cast<__half*>(smem + WH_OFF);
    __half* Xh[2] = { reinterpret_cast<__half*>(smem + XH0_OFF),
                      reinterpret_cast<__half*>(smem + XH1_OFF) };

    int tid = threadIdx.x, wid = tid >> 5, lane = tid & 31;
    int lr = lane >> 2, lc = lane & 3;
    int warp_m = wid & 7, warp_n = wid >> 3;      // M-sixteenth / N-half
    int wbase = warp_m * 16;                      // this warp's 16 output rows
    int n0 = warp_n * 64;                         // this warp's 64 site columns

    // ldmatrix per-thread address components
    int li = lane & 7, lg = lane >> 3;
    // A: (lg&1)->m-half, (lg>>1)->k-half
    uint32_t aBase = smem_u32(Wh) +
        (uint32_t)(((wbase + (lg & 1) * 8 + li) * SROWH + (lg >> 1) * 8) * 2);
    // B: (lg>>1)->n-half(within 16-col group), (lg&1)->k-half
    uint32_t xoff = (uint32_t)(((n0 + (lg >> 1) * 8 + li) * SROWH + (lg & 1) * 8) * 2);
    uint32_t xBase[2] = { smem_u32(Xh[0]) + xoff, smem_u32(Xh[1]) + xoff };

    load_x(Xh[0], x, g_tile_l0[base], g_tile_l1[base], tid);
    load_w(Wh, weight, ch0, tid);
    int cur_ch = ch0;
    float br0 = bias[ch0 * C_DIM + wbase + lr];
    float br1 = bias[ch0 * C_DIM + wbase + lr + 8];

    #pragma unroll 1
    for (int t = 0; t < CHUNK; t++) {
        int idx = base + t;
        int ch = g_tile_ch[idx];
        if (ch < 0) break;
        int l0 = g_tile_l0[idx], l1 = g_tile_l1[idx];

        __syncthreads();                           // X(t) STS + prior-tile reads done

        if (ch != cur_ch) {                        // uniform (channel-sorted tiles)
            load_w(Wh, weight, ch, tid);
            br0 = bias[ch * C_DIM + wbase + lr];
            br1 = bias[ch * C_DIM + wbase + lr + 8];
            cur_ch = ch;
            __syncthreads();
        }

        const __half* Xhc = Xh[t & 1];
        uint32_t bB = xBase[t & 1];

        // ---- MMA: 1 m-frag (M16) x 8 n-frags, 8 k-steps of 16 ----
        float acc[8][4];
        #pragma unroll
        for (int nf = 0; nf < 8; nf++)
            #pragma unroll
            for (int j = 0; j < 4; j++) acc[nf][j] = 0.f;

        #pragma unroll
        for (int ks = 0; ks < 8; ks++) {
            uint32_t koff = ks * 32;               // 16 halves per k-step
            uint32_t af[4];
            ldsm_x4(af, aBase + koff);
            #pragma unroll
            for (int p2 = 0; p2 < 4; p2++) {
                uint32_t bf[4];
                ldsm_x4(bf, bB + p2 * (16 * SROWH * 2) + koff);
                mma_f16(acc[2 * p2],     af, &bf[0]);
                mma_f16(acc[2 * p2 + 1], af, &bf[2]);
            }
        }

        // ---- prefetch next X tile (hides under epilogue) ----
        if (t + 1 < CHUNK && g_tile_ch[idx + 1] >= 0)
            load_x(Xh[(t + 1) & 1], x, g_tile_l0[idx + 1], g_tile_l1[idx + 1], tid);

        // ---- direct epilogue: in-register bias+tanh, residual LDS.16, STG.32 ----
        int l = warp_n ? l1 : l0;
        if (l >= 0) {
            float* ob = out + (size_t)l * C_DIM;
            int o = wbase + lr;
            #pragma unroll
            for (int nf = 0; nf < 8; nf++) {
                int col = n0 + nf * 8 + lc * 2;
                int b = col & 63;
                float x00 = __half2float(Xhc[col * SROWH + o]);
                float x01 = __half2float(Xhc[(col + 1) * SROWH + o]);
                float x10 = __half2float(Xhc[col * SROWH + o + 8]);
                float x11 = __half2float(Xhc[(col + 1) * SROWH + o + 8]);
                float* p0 = ob + (size_t)b * (L_DIM * C_DIM) + o;
                float* p1 = p0 + (L_DIM * C_DIM);
                p0[0] = tanh_fast(acc[nf][0] + br0) + x00;
                p1[0] = tanh_fast(acc[nf][1] + br0) + x01;
                p0[8] = tanh_fast(acc[nf][2] + br1) + x10;
                p1[8] = tanh_fast(acc[nf][3] + br1) + x11;
            }
        }
    }
}

extern "C" void kernel_launch(void* const* d_in, const int* in_sizes, int n_in,
                              void* d_out, int out_size) {
    const float* x  = (const float*)d_in[0];
    const void*  ch = d_in[1];
    const float* w  = (const float*)d_in[2];
    const float* b  = (const float*)d_in[3];
    float* out = (float*)d_out;

    cudaFuncSetAttribute(dense_kernel, cudaFuncAttributeMaxDynamicSharedMemorySize, SMEM_TOTAL);
    cudaFuncSetAttribute(prep_all, cudaFuncAttributeMaxDynamicSharedMemorySize, L_DIM * 4);

    const long long Y_ELEMS = (long long)B_DIM * L_DIM * C_DIM;   // 67,108,864 fp32
    prep_all<<<1, 1024, L_DIM * 4>>>(ch, out + Y_ELEMS);
    dense_kernel<<<GRID_DENSE, 512, SMEM_TOTAL>>>(x, w, b, out);
}

// round 14
// speedup vs baseline: 1.0835x; 1.0835x over previous
#include <cuda_runtime.h>
#include <cuda_fp16.h>
#include <cstdint>

#define B_DIM 64
#define L_DIM 8192
#define C_DIM 128
#define NCH   64
#define GRID_DENSE 296                 // 2 CTAs/SM x 148 SMs, exactly 1 wave
#define CHUNK 14                       // tiles per CTA
#define MAX_TILES (GRID_DENSE * CHUNK) // 4144 >= worst-case 4128 real tiles

static __device__ int g_tile_l0[MAX_TILES];
static __device__ int g_tile_l1[MAX_TILES];
static __device__ int g_tile_ch[MAX_TILES];

// ---------------- helpers ----------------
__device__ __forceinline__ uint32_t smem_u32(const void* p) {
    uint32_t a;
    asm("{ .reg .u64 t; cvta.to.shared.u64 t, %1; cvt.u32.u64 %0, t; }" : "=r"(a) : "l"(p));
    return a;
}
__device__ __forceinline__ float tanh_fast(float v) {
    float r; asm("tanh.approx.f32 %0, %1;" : "=f"(r) : "f"(v)); return r;
}
__device__ __forceinline__ void mma_f16(float* d, const uint32_t* a, const uint32_t* b) {
    asm volatile(
        "mma.sync.aligned.m16n8k16.row.col.f32.f16.f16.f32 "
        "{%0,%1,%2,%3}, {%4,%5,%6,%7}, {%8,%9}, {%0,%1,%2,%3};"
        : "+f"(d[0]), "+f"(d[1]), "+f"(d[2]), "+f"(d[3])
        : "r"(a[0]), "r"(a[1]), "r"(a[2]), "r"(a[3]), "r"(b[0]), "r"(b[1]));
}
__device__ __forceinline__ void ldsm_x4(uint32_t* r, uint32_t addr) {
    asm volatile("ldmatrix.sync.aligned.m8n8.x4.shared.b16 {%0,%1,%2,%3}, [%4];"
        : "=r"(r[0]), "=r"(r[1]), "=r"(r[2]), "=r"(r[3]) : "r"(addr));
}
__device__ __forceinline__ void ldsm_x4_t(uint32_t* r, uint32_t addr) {
    asm volatile("ldmatrix.sync.aligned.m8n8.x4.trans.shared.b16 {%0,%1,%2,%3}, [%4];"
        : "=r"(r[0]), "=r"(r[1]), "=r"(r[2]), "=r"(r[3]) : "r"(addr));
}

// ---------------- prep_all: one launch does everything ----------------
__global__ void prep_all(const void* __restrict__ chan_raw, float* __restrict__ tail_out) {
    __shared__ int s_cnt[NCH], s_start[NCH], s_cur[NCH], s_ts[NCH];
    __shared__ int s_zcnt;
    extern __shared__ int s_sorted[];              // 8192 ints (32 KB dynamic)
    int t = threadIdx.x;                           // 1024 threads

    if (t == 0) s_zcnt = 0;
    if (t < NCH) s_cnt[t] = 0;
    for (int i = t; i < MAX_TILES; i += 1024) g_tile_ch[i] = -1;
    __syncthreads();

    if (t < 256) {                                 // dtype sniff
        const int* w32 = (const int*)chan_raw;
        int z = (w32[2 * t + 1] == 0);
        unsigned m = __ballot_sync(0xFFFFFFFF, z);
        if ((t & 31) == 0) atomicAdd(&s_zcnt, __popc(m));
    }
    __syncthreads();
    int is64 = s_zcnt > 128;

    const long long* c64 = (const long long*)chan_raw;
    const int*       c32 = (const int*)chan_raw;

    for (int i = t; i < L_DIM; i += 1024) {        // histogram + channels tail
        long long v = is64 ? c64[i] : (long long)c32[i];
        tail_out[i] = (float)v;
        atomicAdd(&s_cnt[(int)v & (NCH - 1)], 1);
    }
    __syncthreads();

    if (t == 0) {
        int s = 0, ts = 0;
        for (int g = 0; g < NCH; g++) {
            s_start[g] = s; s_cur[g] = s; s_ts[g] = ts;
            s += s_cnt[g]; ts += (s_cnt[g] + 1) >> 1;
        }
    }
    __syncthreads();

    for (int i = t; i < L_DIM; i += 1024) {        // scatter
        int c = (int)(is64 ? c64[i] : (long long)c32[i]) & (NCH - 1);
        int p = atomicAdd(&s_cur[c], 1);
        s_sorted[p] = i;
    }
    __syncthreads();

    int g = t >> 4, j = t & 15;                    // tile build
    int s0 = s_start[g], c = s_cnt[g], ts = s_ts[g];
    for (int i = j; i < (c + 1) / 2; i += 16) {
        g_tile_l0[ts + i] = s_sorted[s0 + 2 * i];
        g_tile_l1[ts + i] = (2 * i + 1 < c) ? s_sorted[s0 + 2 * i + 1] : -1;
        g_tile_ch[ts + i] = g;
    }
}

// ---------------- dense kernel: R12 tiling + ldmatrix.trans residual ----------------
static constexpr int SROWH = 136;                 // fp16 row stride (halfs)
static constexpr int WHBYTES = C_DIM * SROWH * 2; // 34816
static constexpr int WH_OFF  = 0;
static constexpr int XH0_OFF = WHBYTES;
static constexpr int XH1_OFF = 2 * WHBYTES;
static constexpr int SMEM_TOTAL = 3 * WHBYTES;    // 104448 B -> 2 CTAs/SM

// X tile: LDG.128 fp32 -> RN fp16 -> STS.64 (16 float4 / thread @256 thr)
__device__ __forceinline__ void load_x(__half* Xh, const float* __restrict__ x,
                                       int l0, int l1, int tid) {
    #pragma unroll
    for (int i = 0; i < 16; i++) {
        int f = tid + (i << 8);                    // 0..4095 float4s
        int row = f >> 5, k4 = (f & 31) << 2;      // row uniform per warp
        int l = (row >= 64) ? l1 : l0;
        if (l < 0) continue;
        int b = row & 63;
        float4 v = *reinterpret_cast<const float4*>(x + ((size_t)b * L_DIM + l) * C_DIM + k4);
        __half2 h0 = __floats2half2_rn(v.x, v.y);
        __half2 h1 = __floats2half2_rn(v.z, v.w);
        *reinterpret_cast<uint2*>(Xh + row * SROWH + k4) =
            make_uint2(*(uint32_t*)&h0, *(uint32_t*)&h1);
    }
}
__device__ __forceinline__ void load_w(__half* Wh, const float* __restrict__ weight,
                                       int ch, int tid) {
    const float4* Wsrc = reinterpret_cast<const float4*>(weight + (size_t)ch * (C_DIM * C_DIM));
    #pragma unroll
    for (int i = 0; i < 16; i++) {
        int f = tid + (i << 8);
        float4 v = Wsrc[f];
        __half2 h0 = __floats2half2_rn(v.x, v.y);
        __half2 h1 = __floats2half2_rn(v.z, v.w);
        *reinterpret_cast<uint2*>(Wh + (f >> 5) * SROWH + ((f & 31) << 2)) =
            make_uint2(*(uint32_t*)&h0, *(uint32_t*)&h1);
    }
}

__global__ void __launch_bounds__(256, 2) dense_kernel(
    const float* __restrict__ x, const float* __restrict__ weight,
    const float* __restrict__ bias, float* __restrict__ out)
{
    int base = blockIdx.x * CHUNK;
    int ch0 = g_tile_ch[base];
    if (ch0 < 0) return;

    extern __shared__ char smem[];
    __half* Wh    = reinterpret_cast<__half*>(smem + WH_OFF);
    __half* Xh[2] = { reinterpret_cast<__half*>(smem + XH0_OFF),
                      reinterpret_cast<__half*>(smem + XH1_OFF) };

    int tid = threadIdx.x, wid = tid >> 5, lane = tid & 31;
    int lr = lane >> 2, lc = lane & 3;
    int warp_m = wid & 3, warp_n = wid >> 2;      // M-quadrant / N-half
    int wbase = warp_m * 32;
    int n0 = warp_n * 64;

    // ldmatrix per-thread address components (mainloop fragments)
    int li = lane & 7, lg = lane >> 3;
    uint32_t aBase = smem_u32(Wh) +
        (uint32_t)(((wbase + (lg & 1) * 8 + li) * SROWH + (lg >> 1) * 8) * 2);
    uint32_t xoff = (uint32_t)(((n0 + (lg >> 1) * 8 + li) * SROWH + (lg & 1) * 8) * 2);
    uint32_t xBase[2] = { smem_u32(Xh[0]) + xoff, smem_u32(Xh[1]) + xoff };
    // trans-residual per-thread component: stored-row (X col) from (lg&1)*8+li,
    // o-half from lg>>1
    uint32_t toff = (uint32_t)((((lg & 1) * 8 + li) * SROWH + ((lg >> 1) * 8)) * 2);
    uint32_t tBase[2] = { smem_u32(Xh[0]) + toff, smem_u32(Xh[1]) + toff };

    load_x(Xh[0], x, g_tile_l0[base], g_tile_l1[base], tid);
    load_w(Wh, weight, ch0, tid);
    int cur_ch = ch0;
    float br[2][2];
    #pragma unroll
    for (int mf = 0; mf < 2; mf++) {
        br[mf][0] = bias[ch0 * C_DIM + wbase + mf * 16 + lr];
        br[mf][1] = bias[ch0 * C_DIM + wbase + mf * 16 + lr + 8];
    }

    #pragma unroll 1
    for (int t = 0; t < CHUNK; t++) {
        int idx = base + t;
        int ch = g_tile_ch[idx];
        if (ch < 0) break;
        int l0 = g_tile_l0[idx], l1 = g_tile_l1[idx];

        __syncthreads();                           // X(t) STS + prior-tile reads done

        if (ch != cur_ch) {                        // uniform (channel-sorted tiles)
            load_w(Wh, weight, ch, tid);
            #pragma unroll
            for (int mf = 0; mf < 2; mf++) {
                br[mf][0] = bias[ch * C_DIM + wbase + mf * 16 + lr];
                br[mf][1] = bias[ch * C_DIM + wbase + mf * 16 + lr + 8];
            }
            cur_ch = ch;
            __syncthreads();
        }

        uint32_t bB = xBase[t & 1];
        uint32_t tB = tBase[t & 1];

        // ---- MMA via ldmatrix: 2 m-frags x 8 n-frags, 8 k-steps of 16 ----
        float acc[2][8][4];
        #pragma unroll
        for (int mf = 0; mf < 2; mf++)
            #pragma unroll
            for (int nf = 0; nf < 8; nf++)
                #pragma unroll
                for (int j = 0; j < 4; j++) acc[mf][nf][j] = 0.f;

        #pragma unroll
        for (int ks = 0; ks < 8; ks++) {
            uint32_t koff = ks * 32;               // 16 halves per k-step
            uint32_t bf[4][4];
            #pragma unroll
            for (int p2 = 0; p2 < 4; p2++)
                ldsm_x4(bf[p2], bB + p2 * (16 * SROWH * 2) + koff);
            uint32_t af[2][4];
            #pragma unroll
            for (int mf = 0; mf < 2; mf++)
                ldsm_x4(af[mf], aBase + mf * (16 * SROWH * 2) + koff);
            #pragma unroll
            for (int mf = 0; mf < 2; mf++)
                #pragma unroll
                for (int nf = 0; nf < 8; nf++)
                    mma_f16(acc[mf][nf], af[mf], &bf[nf >> 1][(nf & 1) * 2]);
        }

        // ---- prefetch next X tile (hides under epilogue) ----
        if (t + 1 < CHUNK && g_tile_ch[idx + 1] >= 0)
            load_x(Xh[(t + 1) & 1], x, g_tile_l0[idx + 1], g_tile_l1[idx + 1], tid);

        // ---- direct epilogue: trans-ldmatrix residual, in-register bias+tanh ----
        int l = warp_n ? l1 : l0;
        if (l >= 0) {
            float* ob = out + (size_t)l * C_DIM;
            #pragma unroll
            for (int mf = 0; mf < 2; mf++) {
                int o = wbase + mf * 16 + lr;
                int o0 = wbase + mf * 16;
                #pragma unroll
                for (int nfp = 0; nfp < 4; nfp++) {
                    int colbase = n0 + nfp * 16;
                    uint32_t rx[4];
                    ldsm_x4_t(rx, tB + (uint32_t)((colbase * SROWH + o0) * 2));
                    // rx[0]=nf_even c0c1, rx[1]=nf_odd c0c1, rx[2]=nf_even c2c3, rx[3]=nf_odd c2c3
                    #pragma unroll
                    for (int j = 0; j < 2; j++) {
                        int nf = nfp * 2 + j;
                        float2 x01 = __half22float2(*reinterpret_cast<__half2*>(&rx[j]));
                        float2 x23 = __half22float2(*reinterpret_cast<__half2*>(&rx[2 + j]));
                        int col = n0 + nf * 8 + lc * 2;
                        int b = col & 63;
                        float* p0 = ob + (size_t)b * (L_DIM * C_DIM) + o;
                        float* p1 = p0 + (L_DIM * C_DIM);
                        p0[0] = tanh_fast(acc[mf][nf][0] + br[mf][0]) + x01.x;
                        p1[0] = tanh_fast(acc[mf][nf][1] + br[mf][0]) + x01.y;
                        p0[8] = tanh_fast(acc[mf][nf][2] + br[mf][1]) + x23.x;
                        p1[8] = tanh_fast(acc[mf][nf][3] + br[mf][1]) + x23.y;
                    }
                }
            }
        }
    }
}

extern "C" void kernel_launch(void* const* d_in, const int* in_sizes, int n_in,
                              void* d_out, int out_size) {
    const float* x  = (const float*)d_in[0];
    const void*  ch = d_in[1];
    const float* w  = (const float*)d_in[2];
    const float* b  = (const float*)d_in[3];
    float* out = (float*)d_out;

    cudaFuncSetAttribute(dense_kernel, cudaFuncAttributeMaxDynamicSharedMemorySize, SMEM_TOTAL);
    cudaFuncSetAttribute(prep_all, cudaFuncAttributeMaxDynamicSharedMemorySize, L_DIM * 4);

    const long long Y_ELEMS = (long long)B_DIM * L_DIM * C_DIM;   // 67,108,864 fp32
    prep_all<<<1, 1024, L_DIM * 4>>>(ch, out + Y_ELEMS);
    dense_kernel<<<GRID_DENSE, 256, SMEM_TOTAL>>>(x, w, b, out);
}

// round 15
// speedup vs baseline: 1.0860x; 1.0023x over previous
#include <cuda_runtime.h>
#include <cuda_fp16.h>
#include <cstdint>

#define B_DIM 64
#define L_DIM 8192
#define C_DIM 128
#define NCH   64
#define GRID_DENSE 296                 // 2 CTAs/SM x 148 SMs, exactly 1 wave
#define CHUNK 14                       // tiles per CTA
#define MAX_TILES (GRID_DENSE * CHUNK) // 4144 >= worst-case 4128 real tiles

static __device__ int g_tile_l0[MAX_TILES];
static __device__ int g_tile_l1[MAX_TILES];
static __device__ int g_tile_ch[MAX_TILES];

// ---------------- helpers ----------------
__device__ __forceinline__ uint32_t smem_u32(const void* p) {
    uint32_t a;
    asm("{ .reg .u64 t; cvta.to.shared.u64 t, %1; cvt.u32.u64 %0, t; }" : "=r"(a) : "l"(p));
    return a;
}
__device__ __forceinline__ float tanh_fast(float v) {
    float r; asm("tanh.approx.f32 %0, %1;" : "=f"(r) : "f"(v)); return r;
}
__device__ __forceinline__ void mma_f16(float* d, const uint32_t* a, const uint32_t* b) {
    asm volatile(
        "mma.sync.aligned.m16n8k16.row.col.f32.f16.f16.f32 "
        "{%0,%1,%2,%3}, {%4,%5,%6,%7}, {%8,%9}, {%0,%1,%2,%3};"
        : "+f"(d[0]), "+f"(d[1]), "+f"(d[2]), "+f"(d[3])
        : "r"(a[0]), "r"(a[1]), "r"(a[2]), "r"(a[3]), "r"(b[0]), "r"(b[1]));
}
__device__ __forceinline__ void ldsm_x4(uint32_t* r, uint32_t addr) {
    asm volatile("ldmatrix.sync.aligned.m8n8.x4.shared.b16 {%0,%1,%2,%3}, [%4];"
        : "=r"(r[0]), "=r"(r[1]), "=r"(r[2]), "=r"(r[3]) : "r"(addr));
}
__device__ __forceinline__ void ldsm_x4_t(uint32_t* r, uint32_t addr) {
    asm volatile("ldmatrix.sync.aligned.m8n8.x4.trans.shared.b16 {%0,%1,%2,%3}, [%4];"
        : "=r"(r[0]), "=r"(r[1]), "=r"(r[2]), "=r"(r[3]) : "r"(addr));
}

// ---------------- prep_all: one launch does everything ----------------
__global__ void prep_all(const void* __restrict__ chan_raw, float* __restrict__ tail_out) {
    __shared__ int s_cnt[NCH], s_start[NCH], s_cur[NCH], s_ts[NCH];
    __shared__ int s_zcnt;
    extern __shared__ int s_sorted[];              // 8192 ints (32 KB dynamic)
    int t = threadIdx.x;                           // 1024 threads

    if (t == 0) s_zcnt = 0;
    if (t < NCH) s_cnt[t] = 0;
    for (int i = t; i < MAX_TILES; i += 1024) g_tile_ch[i] = -1;
    __syncthreads();

    if (t < 256) {                                 // dtype sniff
        const int* w32 = (const int*)chan_raw;
        int z = (w32[2 * t + 1] == 0);
        unsigned m = __ballot_sync(0xFFFFFFFF, z);
        if ((t & 31) == 0) atomicAdd(&s_zcnt, __popc(m));
    }
    __syncthreads();
    int is64 = s_zcnt > 128;

    const long long* c64 = (const long long*)chan_raw;
    const int*       c32 = (const int*)chan_raw;

    for (int i = t; i < L_DIM; i += 1024) {        // histogram + channels tail
        long long v = is64 ? c64[i] : (long long)c32[i];
        tail_out[i] = (float)v;
        atomicAdd(&s_cnt[(int)v & (NCH - 1)], 1);
    }
    __syncthreads();

    if (t == 0) {
        int s = 0, ts = 0;
        for (int g = 0; g < NCH; g++) {
            s_start[g] = s; s_cur[g] = s; s_ts[g] = ts;
            s += s_cnt[g]; ts += (s_cnt[g] + 1) >> 1;
        }
    }
    __syncthreads();

    for (int i = t; i < L_DIM; i += 1024) {        // scatter
        int c = (int)(is64 ? c64[i] : (long long)c32[i]) & (NCH - 1);
        int p = atomicAdd(&s_cur[c], 1);
        s_sorted[p] = i;
    }
    __syncthreads();

    int g = t >> 4, j = t & 15;                    // tile build
    int s0 = s_start[g], c = s_cnt[g], ts = s_ts[g];
    for (int i = j; i < (c + 1) / 2; i += 16) {
        g_tile_l0[ts + i] = s_sorted[s0 + 2 * i];
        g_tile_l1[ts + i] = (2 * i + 1 < c) ? s_sorted[s0 + 2 * i + 1] : -1;
        g_tile_ch[ts + i] = g;
    }
}

// ---------------- dense kernel: R12 tiling + ldmatrix.trans residual ----------------
static constexpr int SROWH = 136;                 // fp16 row stride (halfs)
static constexpr int WHBYTES = C_DIM * SROWH * 2; // 34816
static constexpr int WH_OFF  = 0;
static constexpr int XH0_OFF = WHBYTES;
static constexpr int XH1_OFF = 2 * WHBYTES;
static constexpr int SMEM_TOTAL = 3 * WHBYTES;    // 104448 B -> 2 CTAs/SM

// X tile: LDG.128 fp32 -> RN fp16 -> STS.64 (16 float4 / thread @256 thr)
__device__ __forceinline__ void load_x(__half* Xh, const float* __restrict__ x,
                                       int l0, int l1, int tid) {
    #pragma unroll
    for (int i = 0; i < 16; i++) {
        int f = tid + (i << 8);                    // 0..4095 float4s
        int row = f >> 5, k4 = (f & 31) << 2;      // row uniform per warp
        int l = (row >= 64) ? l1 : l0;
        if (l < 0) continue;
        int b = row & 63;
        float4 v = *reinterpret_cast<const float4*>(x + ((size_t)b * L_DIM + l) * C_DIM + k4);
        __half2 h0 = __floats2half2_rn(v.x, v.y);
        __half2 h1 = __floats2half2_rn(v.z, v.w);
        *reinterpret_cast<uint2*>(Xh + row * SROWH + k4) =
            make_uint2(*(uint32_t*)&h0, *(uint32_t*)&h1);
    }
}
__device__ __forceinline__ void load_w(__half* Wh, const float* __restrict__ weight,
                                       int ch, int tid) {
    const float4* Wsrc = reinterpret_cast<const float4*>(weight + (size_t)ch * (C_DIM * C_DIM));
    #pragma unroll
    for (int i = 0; i < 16; i++) {
        int f = tid + (i << 8);
        float4 v = Wsrc[f];
        __half2 h0 = __floats2half2_rn(v.x, v.y);
        __half2 h1 = __floats2half2_rn(v.z, v.w);
        *reinterpret_cast<uint2*>(Wh + (f >> 5) * SROWH + ((f & 31) << 2)) =
            make_uint2(*(uint32_t*)&h0, *(uint32_t*)&h1);
    }
}

__global__ void __launch_bounds__(256, 2) dense_kernel(
    const float* __restrict__ x, const float* __restrict__ weight,
    const float* __restrict__ bias, float* __restrict__ out)
{
    int base = blockIdx.x * CHUNK;
    int ch0 = g_tile_ch[base];
    if (ch0 < 0) return;

    extern __shared__ char smem[];
    __half* Wh    = reinterpret_cast<__half*>(smem + WH_OFF);
    __half* Xh[2] = { reinterpret_cast<__half*>(smem + XH0_OFF),
                      reinterpret_cast<__half*>(smem + XH1_OFF) };

    int tid = threadIdx.x, wid = tid >> 5, lane = tid & 31;
    int lr = lane >> 2, lc = lane & 3;
    int warp_m = wid & 3, warp_n = wid >> 2;      // M-quadrant / N-half
    int wbase = warp_m * 32;
    int n0 = warp_n * 64;

    // ldmatrix per-thread address components (mainloop fragments)
    int li = lane & 7, lg = lane >> 3;
    uint32_t aBase = smem_u32(Wh) +
        (uint32_t)(((wbase + (lg & 1) * 8 + li) * SROWH + (lg >> 1) * 8) * 2);
    uint32_t xoff = (uint32_t)(((n0 + (lg >> 1) * 8 + li) * SROWH + (lg & 1) * 8) * 2);
    uint32_t xBase[2] = { smem_u32(Xh[0]) + xoff, smem_u32(Xh[1]) + xoff };
    // trans-residual per-thread component: stored-row (X col) from (lg&1)*8+li,
    // o-half from lg>>1
    uint32_t toff = (uint32_t)((((lg & 1) * 8 + li) * SROWH + ((lg >> 1) * 8)) * 2);
    uint32_t tBase[2] = { smem_u32(Xh[0]) + toff, smem_u32(Xh[1]) + toff };

    load_x(Xh[0], x, g_tile_l0[base], g_tile_l1[base], tid);
    load_w(Wh, weight, ch0, tid);
    int cur_ch = ch0;
    float br[2][2];
    #pragma unroll
    for (int mf = 0; mf < 2; mf++) {
        br[mf][0] = bias[ch0 * C_DIM + wbase + mf * 16 + lr];
        br[mf][1] = bias[ch0 * C_DIM + wbase + mf * 16 + lr + 8];
    }

    #pragma unroll 1
    for (int t = 0; t < CHUNK; t++) {
        int idx = base + t;
        int ch = g_tile_ch[idx];
        if (ch < 0) break;
        int l0 = g_tile_l0[idx], l1 = g_tile_l1[idx];

        __syncthreads();                           // X(t) STS + prior-tile reads done

        if (ch != cur_ch) {                        // uniform (channel-sorted tiles)
            load_w(Wh, weight, ch, tid);
            #pragma unroll
            for (int mf = 0; mf < 2; mf++) {
                br[mf][0] = bias[ch * C_DIM + wbase + mf * 16 + lr];
                br[mf][1] = bias[ch * C_DIM + wbase + mf * 16 + lr + 8];
            }
            cur_ch = ch;
            __syncthreads();
        }

        uint32_t bB = xBase[t & 1];
        uint32_t tB = tBase[t & 1];

        // ---- MMA via ldmatrix: 2 m-frags x 8 n-frags, 8 k-steps of 16 ----
        float acc[2][8][4];
        #pragma unroll
        for (int mf = 0; mf < 2; mf++)
            #pragma unroll
            for (int nf = 0; nf < 8; nf++)
                #pragma unroll
                for (int j = 0; j < 4; j++) acc[mf][nf][j] = 0.f;

        #pragma unroll
        for (int ks = 0; ks < 8; ks++) {
            uint32_t koff = ks * 32;               // 16 halves per k-step
            uint32_t bf[4][4];
            #pragma unroll
            for (int p2 = 0; p2 < 4; p2++)
                ldsm_x4(bf[p2], bB + p2 * (16 * SROWH * 2) + koff);
            uint32_t af[2][4];
            #pragma unroll
            for (int mf = 0; mf < 2; mf++)
                ldsm_x4(af[mf], aBase + mf * (16 * SROWH * 2) + koff);
            #pragma unroll
            for (int mf = 0; mf < 2; mf++)
                #pragma unroll
                for (int nf = 0; nf < 8; nf++)
                    mma_f16(acc[mf][nf], af[mf], &bf[nf >> 1][(nf & 1) * 2]);
        }

        // ---- prefetch next X tile (hides under epilogue) ----
        if (t + 1 < CHUNK && g_tile_ch[idx + 1] >= 0)
            load_x(Xh[(t + 1) & 1], x, g_tile_l0[idx + 1], g_tile_l1[idx + 1], tid);

        // ---- direct epilogue: trans-ldmatrix residual, in-register bias+tanh ----
        int l = warp_n ? l1 : l0;
        if (l >= 0) {
            float* ob = out + (size_t)l * C_DIM;
            #pragma unroll
            for (int mf = 0; mf < 2; mf++) {
                int o = wbase + mf * 16 + lr;
                int o0 = wbase + mf * 16;
                #pragma unroll
                for (int nfp = 0; nfp < 4; nfp++) {
                    int colbase = n0 + nfp * 16;
                    uint32_t rx[4];
                    ldsm_x4_t(rx, tB + (uint32_t)((colbase * SROWH + o0) * 2));
                    // rx[0]=nf_even c0c1, rx[1]=nf_odd c0c1, rx[2]=nf_even c2c3, rx[3]=nf_odd c2c3
                    #pragma unroll
                    for (int j = 0; j < 2; j++) {
                        int nf = nfp * 2 + j;
                        float2 x01 = __half22float2(*reinterpret_cast<__half2*>(&rx[j]));
                        float2 x23 = __half22float2(*reinterpret_cast<__half2*>(&rx[2 + j]));
                        int col = n0 + nf * 8 + lc * 2;
                        int b = col & 63;
                        float* p0 = ob + (size_t)b * (L_DIM * C_DIM) + o;
                        float* p1 = p0 + (L_DIM * C_DIM);
                        p0[0] = tanh_fast(acc[mf][nf][0] + br[mf][0]) + x01.x;
                        p1[0] = tanh_fast(acc[mf][nf][1] + br[mf][0]) + x01.y;
                        p0[8] = tanh_fast(acc[mf][nf][2] + br[mf][1]) + x23.x;
                        p1[8] = tanh_fast(acc[mf][nf][3] + br[mf][1]) + x23.y;
                    }
                }
            }
        }
    }
}

extern "C" void kernel_launch(void* const* d_in, const int* in_sizes, int n_in,
                              void* d_out, int out_size) {
    const float* x  = (const float*)d_in[0];
    const void*  ch = d_in[1];
    const float* w  = (const float*)d_in[2];
    const float* b  = (const float*)d_in[3];
    float* out = (float*)d_out;

    cudaFuncSetAttribute(dense_kernel, cudaFuncAttributeMaxDynamicSharedMemorySize, SMEM_TOTAL);
    cudaFuncSetAttribute(prep_all, cudaFuncAttributeMaxDynamicSharedMemorySize, L_DIM * 4);

    const long long Y_ELEMS = (long long)B_DIM * L_DIM * C_DIM;   // 67,108,864 fp32
    prep_all<<<1, 1024, L_DIM * 4>>>(ch, out + Y_ELEMS);
    dense_kernel<<<GRID_DENSE, 256, SMEM_TOTAL>>>(x, w, b, out);
}